// round 10
// baseline (speedup 1.0000x reference)
#include <cuda_runtime.h>

// DeepPoly ReLU relaxation, elementwise over N=16,777,216 floats.
// inputs: lb, ub, alpha (fp32, N each). output: [out_lb (N) | out_ub (N)] fp32.
//
// HBM-roofline-saturated — TERMINAL KERNEL (benched 3x: 53.31/53.98/53.34us).
// 20 B/elem mandatory traffic (3 reads + 2 writes, no reuse) = 336 MB
// @ 6.3-6.5 TB/s achieved (~80-82% of 8 TB/s spec). Residual gap is DRAM
// read/write turnaround on a 3:2 mix; per B300 microarch the LTS cap is
// path-independent (LDG.cv == TMA) and HBM striding is not a lever, so no
// software path exceeds plain LDG.128/STG.128 here.
//
// Config ledger:
//   R1/R8/R9 (this config):  53.31 / 53.98 / 53.34 us  (noise ±0.7us)
//   R3 (+ldcs/stcs):         53.34  neutral
//   R4 (exact grid, stcs):   53.54  neutral
//   R2 (2 quads/thread):     53.63  regress (regs 40, occ 60%)
//   R5 (512-thr blocks):     54.27  regress (occ 75.8%)
//   256-bit v8 ld/st: rejected on theory (LSU not binding at issue=29%;
//   +regs reproduces R2's occupancy-loss failure mode).
// Shape: 256 thr/block, 16384 blocks, 1 float4/thread, 29 regs, occ ~80%.

__global__ __launch_bounds__(256) void verify_relu_kernel(
    const float4* __restrict__ lb4,
    const float4* __restrict__ ub4,
    const float4* __restrict__ al4,
    float4* __restrict__ olb4,
    float4* __restrict__ oub4,
    int n4)
{
    int i = blockIdx.x * blockDim.x + threadIdx.x;
    if (i >= n4) return;

    float4 lb = lb4[i];
    float4 ub = ub4[i];
    float4 al = al4[i];

    float4 olb, oub;

    #pragma unroll
    for (int k = 0; k < 4; k++) {
        float l = (&lb.x)[k];
        float u = (&ub.x)[k];
        float a = (&al.x)[k];

        float ca    = fminf(fmaxf(a, 0.0f), 1.0f);
        float slope = fmaxf(u / (u - l), 0.0f);

        float uc_diag = (l > 0.0f) ? 1.0f : slope;
        float uc_bias = (l > 0.0f) ? 0.0f : (-(slope * l));
        float lc_diag = (u < 0.0f) ? 0.0f : ca;

        (&olb.x)[k] = l * lc_diag;
        (&oub.x)[k] = fmaf(u, uc_diag, uc_bias);
    }

    olb4[i] = olb;
    oub4[i] = oub;
}

extern "C" void kernel_launch(void* const* d_in, const int* in_sizes, int n_in,
                              void* d_out, int out_size) {
    const float* lb    = (const float*)d_in[0];
    const float* ub    = (const float*)d_in[1];
    const float* alpha = (const float*)d_in[2];
    float* out = (float*)d_out;

    int n  = in_sizes[0];        // 16777216
    int n4 = n / 4;              // 4194304

    float* out_lb = out;
    float* out_ub = out + n;

    int threads = 256;
    int blocks  = (n4 + threads - 1) / threads;   // 16384

    verify_relu_kernel<<<blocks, threads>>>(
        (const float4*)lb, (const float4*)ub, (const float4*)alpha,
        (float4*)out_lb, (float4*)out_ub, n4);
}

// round 11
// speedup vs baseline: 1.0006x; 1.0006x over previous
#include <cuda_runtime.h>

// DeepPoly ReLU relaxation, elementwise over N=16,777,216 floats.
// inputs: lb, ub, alpha (fp32, N each). output: [out_lb (N) | out_ub (N)] fp32.
//
// HBM-roofline-saturated. 20 B/elem mandatory traffic (3 reads + 2 writes,
// no reuse) = 336 MB @ 6.3-6.5 TB/s achieved (~80% of 8 TB/s spec). Residual
// is DRAM r/w turnaround on a 3:2 mix (not software-addressable: LTS cap is
// path-independent, HBM striding is not a lever per B300 microarch).
//
// Config ledger:
//   R1/R8/R9/R10 (256 thr): 53.31 / 53.98 / 53.34 / 53.73 us (noise ±0.7)
//   R3 (+ldcs/stcs):        53.34  neutral
//   R4 (exact grid, stcs):  53.54  neutral
//   R2 (2 quads/thread):    53.63  regress (occ 60%)
//   R5 (512-thr blocks):    54.27  regress (wave quantization, occ 75.8%)
// This round: 128-thr blocks / 32768 blocks — last unprobed axis. Same regs
// (29) and thr/SM; finer CTA granularity for tail-wave balance and smaller
// per-CTA L1tex load bursts. Expected neutral-to-slightly-better.

__global__ __launch_bounds__(128) void verify_relu_kernel(
    const float4* __restrict__ lb4,
    const float4* __restrict__ ub4,
    const float4* __restrict__ al4,
    float4* __restrict__ olb4,
    float4* __restrict__ oub4,
    int n4)
{
    int i = blockIdx.x * blockDim.x + threadIdx.x;
    if (i >= n4) return;

    float4 lb = lb4[i];
    float4 ub = ub4[i];
    float4 al = al4[i];

    float4 olb, oub;

    #pragma unroll
    for (int k = 0; k < 4; k++) {
        float l = (&lb.x)[k];
        float u = (&ub.x)[k];
        float a = (&al.x)[k];

        float ca    = fminf(fmaxf(a, 0.0f), 1.0f);
        float slope = fmaxf(u / (u - l), 0.0f);

        float uc_diag = (l > 0.0f) ? 1.0f : slope;
        float uc_bias = (l > 0.0f) ? 0.0f : (-(slope * l));
        float lc_diag = (u < 0.0f) ? 0.0f : ca;

        (&olb.x)[k] = l * lc_diag;
        (&oub.x)[k] = fmaf(u, uc_diag, uc_bias);
    }

    olb4[i] = olb;
    oub4[i] = oub;
}

extern "C" void kernel_launch(void* const* d_in, const int* in_sizes, int n_in,
                              void* d_out, int out_size) {
    const float* lb    = (const float*)d_in[0];
    const float* ub    = (const float*)d_in[1];
    const float* alpha = (const float*)d_in[2];
    float* out = (float*)d_out;

    int n  = in_sizes[0];        // 16777216
    int n4 = n / 4;              // 4194304

    float* out_lb = out;
    float* out_ub = out + n;

    int threads = 128;
    int blocks  = (n4 + threads - 1) / threads;   // 32768

    verify_relu_kernel<<<blocks, threads>>>(
        (const float4*)lb, (const float4*)ub, (const float4*)alpha,
        (float4*)out_lb, (float4*)out_ub, n4);
}

// round 12
// speedup vs baseline: 1.0024x; 1.0018x over previous
#include <cuda_runtime.h>

// DeepPoly ReLU relaxation, elementwise over N=16,777,216 floats.
// inputs: lb, ub, alpha (fp32, N each). output: [out_lb (N) | out_ub (N)] fp32.
//
// HBM-roofline-saturated — FINAL KERNEL.
// 20 B/elem mandatory traffic (3 reads + 2 writes, no reuse) = 336 MB
// @ 6.3-6.5 TB/s achieved (~80-82% of 8 TB/s spec). Residual is DRAM
// read/write turnaround on a 3:2 mix; not software-addressable (LTS cap is
// path-independent, HBM striding is not a lever per B300 microarch).
//
// Full config ledger (dur_us end-to-end; kernel-only in parens):
//   R11 (128 thr, this config): 53.70 (43.55, occ 84.3%)  <- best kernel time
//   R1/R8/R9/R10 (256 thr):     53.31/53.98/53.34/53.73 (43.6-45.3)
//   R3 (+ldcs/stcs):            53.34  neutral
//   R4 (exact grid, stcs):      53.54  neutral
//   R2 (2 quads/thread):        53.63  regress (regs 40, occ 60%)
//   R5 (512-thr blocks):        54.27  regress (occ 75.8%)
//   256-bit v8 ld/st:           rejected (reg pressure = R2 failure mode)
// All passing configs are within ±0.7us noise; DRAM pinned at 79-82% spec.
// Shape: 128 thr/block, 32768 blocks, 1 float4/thread, 29 regs.

__global__ __launch_bounds__(128) void verify_relu_kernel(
    const float4* __restrict__ lb4,
    const float4* __restrict__ ub4,
    const float4* __restrict__ al4,
    float4* __restrict__ olb4,
    float4* __restrict__ oub4,
    int n4)
{
    int i = blockIdx.x * blockDim.x + threadIdx.x;
    if (i >= n4) return;

    float4 lb = lb4[i];
    float4 ub = ub4[i];
    float4 al = al4[i];

    float4 olb, oub;

    #pragma unroll
    for (int k = 0; k < 4; k++) {
        float l = (&lb.x)[k];
        float u = (&ub.x)[k];
        float a = (&al.x)[k];

        float ca    = fminf(fmaxf(a, 0.0f), 1.0f);
        float slope = fmaxf(u / (u - l), 0.0f);

        float uc_diag = (l > 0.0f) ? 1.0f : slope;
        float uc_bias = (l > 0.0f) ? 0.0f : (-(slope * l));
        float lc_diag = (u < 0.0f) ? 0.0f : ca;

        (&olb.x)[k] = l * lc_diag;
        (&oub.x)[k] = fmaf(u, uc_diag, uc_bias);
    }

    olb4[i] = olb;
    oub4[i] = oub;
}

extern "C" void kernel_launch(void* const* d_in, const int* in_sizes, int n_in,
                              void* d_out, int out_size) {
    const float* lb    = (const float*)d_in[0];
    const float* ub    = (const float*)d_in[1];
    const float* alpha = (const float*)d_in[2];
    float* out = (float*)d_out;

    int n  = in_sizes[0];        // 16777216
    int n4 = n / 4;              // 4194304

    float* out_lb = out;
    float* out_ub = out + n;

    int threads = 128;
    int blocks  = (n4 + threads - 1) / threads;   // 32768

    verify_relu_kernel<<<blocks, threads>>>(
        (const float4*)lb, (const float4*)ub, (const float4*)alpha,
        (float4*)out_lb, (float4*)out_ub, n4);
}

// round 13
// speedup vs baseline: 1.0078x; 1.0054x over previous
#include <cuda_runtime.h>

// DeepPoly ReLU relaxation, elementwise over N=16,777,216 floats.
// inputs: lb, ub, alpha (fp32, N each). output: [out_lb (N) | out_ub (N)] fp32.
//
// HBM-roofline-saturated. 20 B/elem mandatory traffic (3 reads + 2 writes,
// no reuse) = 336 MB @ 6.3-6.6 TB/s achieved (~80-83% of 8 TB/s spec).
//
// Block-size trend is monotone and measured (kernel-only us, occ):
//   512 thr: 45.4, 75.8%   (R5, regress)
//   256 thr: 43.6-45.3, ~80%  (R1/R8/R9/R10)
//   128 thr: 43.55 / 42.88, 84-85%, DRAM 83.1%  (R11/R12, best)
// Mechanism: finer CTA granularity -> better tail-wave balance + shallower
// per-CTA L1tex bursts (less cross-CTA completion spread). This round probes
// the last step: 64 thr/block, 65536 blocks (32 CTAs/SM = HW max, same
// 2048 thr/SM). If it regresses, 128-thr is the final config.
//
// Other axes settled: hints neutral (R3/R4); 2 quads/thread regress (R2);
// v8 ld/st rejected (reg pressure). 1 float4/thread, 29 regs.

__global__ __launch_bounds__(64) void verify_relu_kernel(
    const float4* __restrict__ lb4,
    const float4* __restrict__ ub4,
    const float4* __restrict__ al4,
    float4* __restrict__ olb4,
    float4* __restrict__ oub4,
    int n4)
{
    int i = blockIdx.x * blockDim.x + threadIdx.x;
    if (i >= n4) return;

    float4 lb = lb4[i];
    float4 ub = ub4[i];
    float4 al = al4[i];

    float4 olb, oub;

    #pragma unroll
    for (int k = 0; k < 4; k++) {
        float l = (&lb.x)[k];
        float u = (&ub.x)[k];
        float a = (&al.x)[k];

        float ca    = fminf(fmaxf(a, 0.0f), 1.0f);
        float slope = fmaxf(u / (u - l), 0.0f);

        float uc_diag = (l > 0.0f) ? 1.0f : slope;
        float uc_bias = (l > 0.0f) ? 0.0f : (-(slope * l));
        float lc_diag = (u < 0.0f) ? 0.0f : ca;

        (&olb.x)[k] = l * lc_diag;
        (&oub.x)[k] = fmaf(u, uc_diag, uc_bias);
    }

    olb4[i] = olb;
    oub4[i] = oub;
}

extern "C" void kernel_launch(void* const* d_in, const int* in_sizes, int n_in,
                              void* d_out, int out_size) {
    const float* lb    = (const float*)d_in[0];
    const float* ub    = (const float*)d_in[1];
    const float* alpha = (const float*)d_in[2];
    float* out = (float*)d_out;

    int n  = in_sizes[0];        // 16777216
    int n4 = n / 4;              // 4194304

    float* out_lb = out;
    float* out_ub = out + n;

    int threads = 64;
    int blocks  = (n4 + threads - 1) / threads;   // 65536

    verify_relu_kernel<<<blocks, threads>>>(
        (const float4*)lb, (const float4*)ub, (const float4*)alpha,
        (float4*)out_lb, (float4*)out_ub, n4);
}